// round 1
// baseline (speedup 1.0000x reference)
#include <cuda_runtime.h>
#include <cstdint>

#define BB      32
#define HH      32
#define KVHH    8
#define DD      128
#define SS      2048
#define REP     4          // HH/KVHH
#define SPLITS  4
#define CHUNK   (SS/SPLITS)        // 512
#define TPB     256
#define NWARPS  8
#define TPW     (CHUNK/NWARPS)     // 64 tokens per warp
#define SCALE_F 0.08838834764831845f   // 1/sqrt(128)

// ---------------- device scratch (no allocs allowed) ----------------
__device__ float g_tab[SS * DD];                        // [pos][0:64]=cos, [64:128]=sin (1 MB)
__device__ float g_pacc[BB * KVHH * SPLITS * REP * DD]; // 2 MB split partials (unnormalized)
__device__ float g_pm[BB * KVHH * SPLITS * REP];
__device__ float g_pl[BB * KVHH * SPLITS * REP];

// ---------------- rope table ----------------
__global__ void rope_table_kernel() {
    int idx = blockIdx.x * blockDim.x + threadIdx.x;    // SS*64
    if (idx >= SS * 64) return;
    int pos = idx >> 6, i = idx & 63;
    // inv_freq = 10000^(-i/64) = 2^(-i * log2(10000)/64)
    float inv = exp2f(-(float)i * (13.287712379549449f / 64.0f));
    float ang = (float)pos * inv;
    g_tab[pos * DD + i]      = cosf(ang);
    g_tab[pos * DD + 64 + i] = sinf(ang);
}

__device__ __forceinline__ float4 shfl_xor_f4(float4 v, int m) {
    float4 r;
    r.x = __shfl_xor_sync(0xffffffffu, v.x, m);
    r.y = __shfl_xor_sync(0xffffffffu, v.y, m);
    r.z = __shfl_xor_sync(0xffffffffu, v.z, m);
    r.w = __shfl_xor_sync(0xffffffffu, v.w, m);
    return r;
}

// ---------------- main split attention kernel ----------------
__global__ void __launch_bounds__(TPB, 2)
paged_attn_main(const float* __restrict__ query,
                const float* __restrict__ k_cache,
                const float* __restrict__ v_cache,
                const int*   __restrict__ slot_mapping,
                const int*   __restrict__ positions)
{
    const int cta   = blockIdx.x;
    const int split = cta & (SPLITS - 1);
    const int kvh   = (cta >> 2) & (KVHH - 1);
    const int b     = cta >> 5;
    const int tid   = threadIdx.x;
    const int w     = tid >> 5;
    const int lane  = tid & 31;

    __shared__ __align__(16) float4 s_scores[NWARPS][TPW];          // 8 KB
    __shared__ __align__(16) float  s_acc[REP][NWARPS][DD];         // 16 KB
    __shared__ float s_m[NWARPS][REP], s_l[NWARPS][REP];
    __shared__ float s_mstar[REP], s_f[NWARPS][REP];

    const int  i4   = (lane & 15) << 2;      // rope freq-index base for this lane
    const float sign = (lane < 16) ? -1.0f : 1.0f;

    // ---- roped + pre-scaled Q, 4 heads, 4 comps per lane ----
    const int posQ = positions[b * SS + (SS - 1)];
    const float4 cq = *(const float4*)(g_tab + posQ * DD + i4);
    const float4 sq = *(const float4*)(g_tab + posQ * DD + 64 + i4);
    float4 qr[REP];
#pragma unroll
    for (int r = 0; r < REP; r++) {
        int h = kvh * REP + r;
        float4 q = *(const float4*)(query + ((size_t)b * HH + h) * DD + lane * 4);
        float4 o = shfl_xor_f4(q, 16);
        float4 v;
        v.x = (fmaf(sign * o.x, sq.x, q.x * cq.x)) * SCALE_F;
        v.y = (fmaf(sign * o.y, sq.y, q.y * cq.y)) * SCALE_F;
        v.z = (fmaf(sign * o.z, sq.z, q.z * cq.z)) * SCALE_F;
        v.w = (fmaf(sign * o.w, sq.w, q.w * cq.w)) * SCALE_F;
        qr[r] = v;
    }

    const int sbase = split * CHUNK + w * TPW;
    const int map_base = b * SS + sbase;
    const float* kbase = k_cache + kvh * DD + lane * 4;
    const float* vbase = v_cache + kvh * DD + lane * 4;

    // ================= pass 1: K, scores -> smem, per-head max =================
    float4 mmax = make_float4(-1e30f, -1e30f, -1e30f, -1e30f);
#pragma unroll 4
    for (int t = 0; t < TPW; t++) {
        int slot = slot_mapping[map_base + t];
        int pos  = positions[map_base + t];
        float4 k4 = make_float4(0.f, 0.f, 0.f, 0.f);
        if (slot >= 0) k4 = *(const float4*)(kbase + (size_t)slot * (KVHH * DD));
        float4 c4 = *(const float4*)(g_tab + pos * DD + i4);
        float4 n4 = *(const float4*)(g_tab + pos * DD + 64 + i4);
        float4 o  = shfl_xor_f4(k4, 16);
        float4 kr;
        kr.x = fmaf(sign * o.x, n4.x, k4.x * c4.x);
        kr.y = fmaf(sign * o.y, n4.y, k4.y * c4.y);
        kr.z = fmaf(sign * o.z, n4.z, k4.z * c4.z);
        kr.w = fmaf(sign * o.w, n4.w, k4.w * c4.w);

        float4 dd;
        dd.x = fmaf(kr.w, qr[0].w, fmaf(kr.z, qr[0].z, fmaf(kr.y, qr[0].y, kr.x * qr[0].x)));
        dd.y = fmaf(kr.w, qr[1].w, fmaf(kr.z, qr[1].z, fmaf(kr.y, qr[1].y, kr.x * qr[1].x)));
        dd.z = fmaf(kr.w, qr[2].w, fmaf(kr.z, qr[2].z, fmaf(kr.y, qr[2].y, kr.x * qr[2].x)));
        dd.w = fmaf(kr.w, qr[3].w, fmaf(kr.z, qr[3].z, fmaf(kr.y, qr[3].y, kr.x * qr[3].x)));
#pragma unroll
        for (int off = 16; off; off >>= 1) {
            float4 s = shfl_xor_f4(dd, off);
            dd.x += s.x; dd.y += s.y; dd.z += s.z; dd.w += s.w;
        }
        mmax.x = fmaxf(mmax.x, dd.x);
        mmax.y = fmaxf(mmax.y, dd.y);
        mmax.z = fmaxf(mmax.z, dd.z);
        mmax.w = fmaxf(mmax.w, dd.w);
        if (lane == 0) s_scores[w][t] = dd;
    }
    __syncwarp();

    // ================= pass 2: V, exp + accumulate =================
    float4 l4 = make_float4(0.f, 0.f, 0.f, 0.f);
    float4 acc0 = make_float4(0.f,0.f,0.f,0.f), acc1 = acc0, acc2 = acc0, acc3 = acc0;
#pragma unroll 4
    for (int t = 0; t < TPW; t++) {
        int slot = slot_mapping[map_base + t];
        float4 v4 = make_float4(0.f, 0.f, 0.f, 0.f);
        if (slot >= 0) v4 = *(const float4*)(vbase + (size_t)slot * (KVHH * DD));
        float4 sc = s_scores[w][t];
        float p0 = __expf(sc.x - mmax.x);
        float p1 = __expf(sc.y - mmax.y);
        float p2 = __expf(sc.z - mmax.z);
        float p3 = __expf(sc.w - mmax.w);
        l4.x += p0; l4.y += p1; l4.z += p2; l4.w += p3;
        acc0.x = fmaf(p0, v4.x, acc0.x); acc0.y = fmaf(p0, v4.y, acc0.y);
        acc0.z = fmaf(p0, v4.z, acc0.z); acc0.w = fmaf(p0, v4.w, acc0.w);
        acc1.x = fmaf(p1, v4.x, acc1.x); acc1.y = fmaf(p1, v4.y, acc1.y);
        acc1.z = fmaf(p1, v4.z, acc1.z); acc1.w = fmaf(p1, v4.w, acc1.w);
        acc2.x = fmaf(p2, v4.x, acc2.x); acc2.y = fmaf(p2, v4.y, acc2.y);
        acc2.z = fmaf(p2, v4.z, acc2.z); acc2.w = fmaf(p2, v4.w, acc2.w);
        acc3.x = fmaf(p3, v4.x, acc3.x); acc3.y = fmaf(p3, v4.y, acc3.y);
        acc3.z = fmaf(p3, v4.z, acc3.z); acc3.w = fmaf(p3, v4.w, acc3.w);
    }

    // ---- per-warp state to smem ----
    if (lane == 0) {
        s_m[w][0] = mmax.x; s_m[w][1] = mmax.y; s_m[w][2] = mmax.z; s_m[w][3] = mmax.w;
        s_l[w][0] = l4.x;   s_l[w][1] = l4.y;   s_l[w][2] = l4.z;   s_l[w][3] = l4.w;
    }
    *(float4*)&s_acc[0][w][lane * 4] = acc0;
    *(float4*)&s_acc[1][w][lane * 4] = acc1;
    *(float4*)&s_acc[2][w][lane * 4] = acc2;
    *(float4*)&s_acc[3][w][lane * 4] = acc3;
    __syncthreads();

    // ---- cross-warp softmax merge ----
    if (tid < REP) {
        float ms = -1e30f;
#pragma unroll
        for (int ww = 0; ww < NWARPS; ww++) ms = fmaxf(ms, s_m[ww][tid]);
        s_mstar[tid] = ms;
    }
    __syncthreads();
    if (tid < NWARPS * REP) {
        int ww = tid >> 2, h = tid & 3;
        s_f[ww][h] = __expf(s_m[ww][h] - s_mstar[h]);
    }
    __syncthreads();

    const size_t pidx = (size_t)((b * KVHH + kvh) * SPLITS + split);
    const size_t obase = pidx * (REP * DD);
    for (int idx = tid; idx < REP * DD; idx += TPB) {
        int h = idx >> 7, d = idx & (DD - 1);
        float v = 0.f;
#pragma unroll
        for (int ww = 0; ww < NWARPS; ww++) v = fmaf(s_f[ww][h], s_acc[h][ww][d], v);
        g_pacc[obase + idx] = v;
    }
    if (tid < REP) {
        float ls = 0.f;
#pragma unroll
        for (int ww = 0; ww < NWARPS; ww++) ls = fmaf(s_f[ww][tid], s_l[ww][tid], ls);
        g_pm[pidx * REP + tid] = s_mstar[tid];
        g_pl[pidx * REP + tid] = ls;
    }
}

// ---------------- split combine ----------------
__global__ void combine_kernel(float* __restrict__ out) {
    int idx = blockIdx.x * blockDim.x + threadIdx.x;
    if (idx >= BB * HH * DD) return;
    int d = idx & (DD - 1);
    int h = (idx >> 7) & (HH - 1);
    int b = idx >> 12;
    int kvh = h >> 2, r = h & 3;
    int pbase = (b * KVHH + kvh) * SPLITS;

    float mv[SPLITS];
    float ms = -1e30f;
#pragma unroll
    for (int s = 0; s < SPLITS; s++) {
        mv[s] = g_pm[(pbase + s) * REP + r];
        ms = fmaxf(ms, mv[s]);
    }
    float num = 0.f, den = 0.f;
#pragma unroll
    for (int s = 0; s < SPLITS; s++) {
        float f = __expf(mv[s] - ms);
        den = fmaf(f, g_pl[(pbase + s) * REP + r], den);
        num = fmaf(f, g_pacc[(size_t)(pbase + s) * REP * DD + r * DD + d], num);
    }
    out[idx] = num / den;
}

// ---------------- launch ----------------
extern "C" void kernel_launch(void* const* d_in, const int* in_sizes, int n_in,
                              void* d_out, int out_size) {
    const float* query  = (const float*)d_in[0];
    const float* kcache = (const float*)d_in[1];
    const float* vcache = (const float*)d_in[2];
    const int*   slots  = (const int*)d_in[3];
    const int*   poss   = (const int*)d_in[4];

    rope_table_kernel<<<(SS * 64 + 255) / 256, 256>>>();
    paged_attn_main<<<BB * KVHH * SPLITS, TPB>>>(query, kcache, vcache, slots, poss);
    combine_kernel<<<(BB * HH * DD + 255) / 256, 256>>>((float*)d_out);
}

// round 2
// speedup vs baseline: 1.0459x; 1.0459x over previous
#include <cuda_runtime.h>
#include <cstdint>

#define BB      32
#define HH      32
#define KVHH    8
#define DD      128
#define SS      2048
#define REP     4          // HH/KVHH
#define SPLITS  4
#define CHUNK   (SS/SPLITS)        // 512
#define TPB     256
#define NWARPS  8
#define TPW     (CHUNK/NWARPS)     // 64 tokens per warp
#define SCALE_F 0.08838834764831845f   // 1/sqrt(128)

// ---------------- device scratch (no allocs allowed) ----------------
__device__ float g_tab[SS * DD];                        // [pos][0:64]=cos, [64:128]=sin (1 MB)
__device__ float g_pacc[BB * KVHH * SPLITS * REP * DD]; // 2 MB split partials (unnormalized)
__device__ float g_pm[BB * KVHH * SPLITS * REP];
__device__ float g_pl[BB * KVHH * SPLITS * REP];

// ---------------- rope table ----------------
__global__ void rope_table_kernel() {
    int idx = blockIdx.x * blockDim.x + threadIdx.x;    // SS*64
    if (idx >= SS * 64) return;
    int pos = idx >> 6, i = idx & 63;
    float inv = exp2f(-(float)i * (13.287712379549449f / 64.0f));
    float ang = (float)pos * inv;
    g_tab[pos * DD + i]      = cosf(ang);
    g_tab[pos * DD + 64 + i] = sinf(ang);
}

__device__ __forceinline__ float4 shfl_xor_f4(float4 v, int m) {
    float4 r;
    r.x = __shfl_xor_sync(0xffffffffu, v.x, m);
    r.y = __shfl_xor_sync(0xffffffffu, v.y, m);
    r.z = __shfl_xor_sync(0xffffffffu, v.z, m);
    r.w = __shfl_xor_sync(0xffffffffu, v.w, m);
    return r;
}

// ---------------- main split attention kernel ----------------
__global__ void __launch_bounds__(TPB, 2)
paged_attn_main(const float* __restrict__ query,
                const float* __restrict__ k_cache,
                const float* __restrict__ v_cache,
                const int*   __restrict__ slot_mapping,
                const int*   __restrict__ positions)
{
    const int cta   = blockIdx.x;
    const int split = cta & (SPLITS - 1);
    const int kvh   = (cta >> 2) & (KVHH - 1);
    const int b     = cta >> 5;
    const int tid   = threadIdx.x;
    const int w     = tid >> 5;
    const int lane  = tid & 31;

    __shared__ __align__(16) float4 s_scores[NWARPS][TPW];          // 8 KB
    __shared__ __align__(16) float  s_acc[REP][NWARPS][DD];         // 16 KB
    __shared__ float s_m[NWARPS][REP], s_l[NWARPS][REP];
    __shared__ float s_mstar[REP], s_f[NWARPS][REP];

    const int  i4   = (lane & 15) << 2;      // rope freq-index base for this lane
    const float sign = (lane < 16) ? -1.0f : 1.0f;

    // ---- roped + pre-scaled Q, 4 heads, 4 comps per lane ----
    const int posQ = positions[b * SS + (SS - 1)];
    const float4 cq = *(const float4*)(g_tab + posQ * DD + i4);
    const float4 sq = *(const float4*)(g_tab + posQ * DD + 64 + i4);
    float4 qr[REP];
#pragma unroll
    for (int r = 0; r < REP; r++) {
        int h = kvh * REP + r;
        float4 q = *(const float4*)(query + ((size_t)b * HH + h) * DD + lane * 4);
        float4 o = shfl_xor_f4(q, 16);
        float4 v;
        v.x = (fmaf(sign * o.x, sq.x, q.x * cq.x)) * SCALE_F;
        v.y = (fmaf(sign * o.y, sq.y, q.y * cq.y)) * SCALE_F;
        v.z = (fmaf(sign * o.z, sq.z, q.z * cq.z)) * SCALE_F;
        v.w = (fmaf(sign * o.w, sq.w, q.w * cq.w)) * SCALE_F;
        qr[r] = v;
    }

    const int sbase = split * CHUNK + w * TPW;
    const int* smap = slot_mapping + b * SS + sbase;
    const int* pmap = positions + b * SS + sbase;
    const float* kbase = k_cache + kvh * DD + lane * 4;
    const float* vbase = v_cache + kvh * DD + lane * 4;

    // ================= pass 1: K, scores -> smem, per-head max =================
    // Each lane ends each token owning the full score for head (lane>>3).
    float mloc = -1e30f;
#pragma unroll 1
    for (int t0 = 0; t0 < TPW; t0 += 4) {
        int sl[4], ps[4];
#pragma unroll
        for (int u = 0; u < 4; u++) { sl[u] = __ldg(smap + t0 + u); ps[u] = __ldg(pmap + t0 + u); }
        float4 kk[4], cc[4], nn[4];
#pragma unroll
        for (int u = 0; u < 4; u++) {
            kk[u] = make_float4(0.f, 0.f, 0.f, 0.f);
            if (sl[u] >= 0) kk[u] = *(const float4*)(kbase + (size_t)sl[u] * (KVHH * DD));
            const float* tr = g_tab + ps[u] * DD + i4;
            cc[u] = *(const float4*)tr;
            nn[u] = *(const float4*)(tr + 64);
        }
#pragma unroll
        for (int u = 0; u < 4; u++) {
            // rope K (sign folded into sin once)
            float4 ss;
            ss.x = sign * nn[u].x; ss.y = sign * nn[u].y;
            ss.z = sign * nn[u].z; ss.w = sign * nn[u].w;
            float4 o = shfl_xor_f4(kk[u], 16);
            float4 kr;
            kr.x = fmaf(o.x, ss.x, kk[u].x * cc[u].x);
            kr.y = fmaf(o.y, ss.y, kk[u].y * cc[u].y);
            kr.z = fmaf(o.z, ss.z, kk[u].z * cc[u].z);
            kr.w = fmaf(o.w, ss.w, kk[u].w * cc[u].w);
            // per-head partial dots
            float v0 = fmaf(kr.w, qr[0].w, fmaf(kr.z, qr[0].z, fmaf(kr.y, qr[0].y, kr.x * qr[0].x)));
            float v1 = fmaf(kr.w, qr[1].w, fmaf(kr.z, qr[1].z, fmaf(kr.y, qr[1].y, kr.x * qr[1].x)));
            float v2 = fmaf(kr.w, qr[2].w, fmaf(kr.z, qr[2].z, fmaf(kr.y, qr[2].y, kr.x * qr[2].x)));
            float v3 = fmaf(kr.w, qr[3].w, fmaf(kr.z, qr[3].z, fmaf(kr.y, qr[3].y, kr.x * qr[3].x)));
            // width-folding reduce: 9 shuffles total
            float r0 = __shfl_xor_sync(0xffffffffu, v0, 16);
            float r1 = __shfl_xor_sync(0xffffffffu, v1, 16);
            float r2 = __shfl_xor_sync(0xffffffffu, v2, 16);
            float r3 = __shfl_xor_sync(0xffffffffu, v3, 16);
            float t0a = v0 + r0, t1a = v1 + r1, t2a = v2 + r2, t3a = v3 + r3;
            float a0 = (lane & 16) ? t2a : t0a;
            float a1 = (lane & 16) ? t3a : t1a;
            float u0 = a0 + __shfl_xor_sync(0xffffffffu, a0, 8);
            float u1 = a1 + __shfl_xor_sync(0xffffffffu, a1, 8);
            float bsum = (lane & 8) ? u1 : u0;
            bsum += __shfl_xor_sync(0xffffffffu, bsum, 4);
            bsum += __shfl_xor_sync(0xffffffffu, bsum, 2);
            bsum += __shfl_xor_sync(0xffffffffu, bsum, 1);
            // bsum = full score for head (lane>>3)
            mloc = fmaxf(mloc, bsum);
            if ((lane & 7) == 0) ((float*)&s_scores[w][t0 + u])[lane >> 3] = bsum;
        }
    }
    __syncwarp();
    // broadcast per-head maxes to all lanes
    const float m0 = __shfl_sync(0xffffffffu, mloc, 0);
    const float m1 = __shfl_sync(0xffffffffu, mloc, 8);
    const float m2 = __shfl_sync(0xffffffffu, mloc, 16);
    const float m3 = __shfl_sync(0xffffffffu, mloc, 24);

    // ================= pass 2: V, exp + accumulate =================
    float4 l4 = make_float4(0.f, 0.f, 0.f, 0.f);
    float4 acc0 = make_float4(0.f,0.f,0.f,0.f), acc1 = acc0, acc2 = acc0, acc3 = acc0;
#pragma unroll 1
    for (int t0 = 0; t0 < TPW; t0 += 4) {
        int sl[4];
#pragma unroll
        for (int u = 0; u < 4; u++) sl[u] = __ldg(smap + t0 + u);
        float4 vv[4], sc[4];
#pragma unroll
        for (int u = 0; u < 4; u++) {
            vv[u] = make_float4(0.f, 0.f, 0.f, 0.f);
            if (sl[u] >= 0) vv[u] = *(const float4*)(vbase + (size_t)sl[u] * (KVHH * DD));
            sc[u] = s_scores[w][t0 + u];
        }
#pragma unroll
        for (int u = 0; u < 4; u++) {
            float p0 = __expf(sc[u].x - m0);
            float p1 = __expf(sc[u].y - m1);
            float p2 = __expf(sc[u].z - m2);
            float p3 = __expf(sc[u].w - m3);
            l4.x += p0; l4.y += p1; l4.z += p2; l4.w += p3;
            float4 v4 = vv[u];
            acc0.x = fmaf(p0, v4.x, acc0.x); acc0.y = fmaf(p0, v4.y, acc0.y);
            acc0.z = fmaf(p0, v4.z, acc0.z); acc0.w = fmaf(p0, v4.w, acc0.w);
            acc1.x = fmaf(p1, v4.x, acc1.x); acc1.y = fmaf(p1, v4.y, acc1.y);
            acc1.z = fmaf(p1, v4.z, acc1.z); acc1.w = fmaf(p1, v4.w, acc1.w);
            acc2.x = fmaf(p2, v4.x, acc2.x); acc2.y = fmaf(p2, v4.y, acc2.y);
            acc2.z = fmaf(p2, v4.z, acc2.z); acc2.w = fmaf(p2, v4.w, acc2.w);
            acc3.x = fmaf(p3, v4.x, acc3.x); acc3.y = fmaf(p3, v4.y, acc3.y);
            acc3.z = fmaf(p3, v4.z, acc3.z); acc3.w = fmaf(p3, v4.w, acc3.w);
        }
    }

    // ---- per-warp state to smem ----
    if ((lane & 7) == 0) s_m[w][lane >> 3] = mloc;
    if (lane == 0) {
        s_l[w][0] = l4.x;   s_l[w][1] = l4.y;   s_l[w][2] = l4.z;   s_l[w][3] = l4.w;
    }
    *(float4*)&s_acc[0][w][lane * 4] = acc0;
    *(float4*)&s_acc[1][w][lane * 4] = acc1;
    *(float4*)&s_acc[2][w][lane * 4] = acc2;
    *(float4*)&s_acc[3][w][lane * 4] = acc3;
    __syncthreads();

    // ---- cross-warp softmax merge ----
    if (tid < REP) {
        float ms = -1e30f;
#pragma unroll
        for (int ww = 0; ww < NWARPS; ww++) ms = fmaxf(ms, s_m[ww][tid]);
        s_mstar[tid] = ms;
    }
    __syncthreads();
    if (tid < NWARPS * REP) {
        int ww = tid >> 2, h = tid & 3;
        s_f[ww][h] = __expf(s_m[ww][h] - s_mstar[h]);
    }
    __syncthreads();

    const size_t pidx = (size_t)((b * KVHH + kvh) * SPLITS + split);
    const size_t obase = pidx * (REP * DD);
    for (int idx = tid; idx < REP * DD; idx += TPB) {
        int h = idx >> 7, d = idx & (DD - 1);
        float v = 0.f;
#pragma unroll
        for (int ww = 0; ww < NWARPS; ww++) v = fmaf(s_f[ww][h], s_acc[h][ww][d], v);
        g_pacc[obase + idx] = v;
    }
    if (tid < REP) {
        float ls = 0.f;
#pragma unroll
        for (int ww = 0; ww < NWARPS; ww++) ls = fmaf(s_f[ww][tid], s_l[ww][tid], ls);
        g_pm[pidx * REP + tid] = s_mstar[tid];
        g_pl[pidx * REP + tid] = ls;
    }
}

// ---------------- split combine ----------------
__global__ void combine_kernel(float* __restrict__ out) {
    int idx = blockIdx.x * blockDim.x + threadIdx.x;
    if (idx >= BB * HH * DD) return;
    int d = idx & (DD - 1);
    int h = (idx >> 7) & (HH - 1);
    int b = idx >> 12;
    int kvh = h >> 2, r = h & 3;
    int pbase = (b * KVHH + kvh) * SPLITS;

    float mv[SPLITS];
    float ms = -1e30f;
#pragma unroll
    for (int s = 0; s < SPLITS; s++) {
        mv[s] = g_pm[(pbase + s) * REP + r];
        ms = fmaxf(ms, mv[s]);
    }
    float num = 0.f, den = 0.f;
#pragma unroll
    for (int s = 0; s < SPLITS; s++) {
        float f = __expf(mv[s] - ms);
        den = fmaf(f, g_pl[(pbase + s) * REP + r], den);
        num = fmaf(f, g_pacc[(size_t)(pbase + s) * REP * DD + r * DD + d], num);
    }
    out[idx] = num / den;
}

// ---------------- launch ----------------
extern "C" void kernel_launch(void* const* d_in, const int* in_sizes, int n_in,
                              void* d_out, int out_size) {
    const float* query  = (const float*)d_in[0];
    const float* kcache = (const float*)d_in[1];
    const float* vcache = (const float*)d_in[2];
    const int*   slots  = (const int*)d_in[3];
    const int*   poss   = (const int*)d_in[4];

    rope_table_kernel<<<(SS * 64 + 255) / 256, 256>>>();
    paged_attn_main<<<BB * KVHH * SPLITS, TPB>>>(query, kcache, vcache, slots, poss);
    combine_kernel<<<(BB * HH * DD + 255) / 256, 256>>>((float*)d_out);
}

// round 3
// speedup vs baseline: 1.3021x; 1.2450x over previous
#include <cuda_runtime.h>
#include <cstdint>

#define BB      32
#define HH      32
#define KVHH    8
#define DD      128
#define SS      2048
#define REP     4          // HH/KVHH
#define SPLITS  8
#define CHUNK   (SS/SPLITS)        // 256
#define TPB     256
#define NWARPS  8
#define TPW     (CHUNK/NWARPS)     // 32 tokens per warp
#define SCALE_F 0.08838834764831845f   // 1/sqrt(128)

// ---------------- device scratch (no allocs allowed) ----------------
// tab4[pos][lane] = {cos(2l), cos(2l+1), sin(2l), sin(2l+1)}  (1 MB)
__device__ float4 g_tab4[SS * 32];
__device__ float g_pacc[BB * KVHH * SPLITS * REP * DD]; // 4 MB split partials
__device__ float g_pm[BB * KVHH * SPLITS * REP];
__device__ float g_pl[BB * KVHH * SPLITS * REP];

// ---------------- rope table ----------------
__global__ void rope_table_kernel() {
    int idx = blockIdx.x * blockDim.x + threadIdx.x;    // SS*32
    if (idx >= SS * 32) return;
    int pos = idx >> 5, l = idx & 31;
    // inv_freq(i) = 10000^(-i/64) ; this lane covers i = 2l, 2l+1
    float inv0 = exp2f(-(float)(2 * l)     * (13.287712379549449f / 64.0f));
    float inv1 = exp2f(-(float)(2 * l + 1) * (13.287712379549449f / 64.0f));
    float a0 = (float)pos * inv0, a1 = (float)pos * inv1;
    float c0, s0, c1, s1;
    sincosf(a0, &s0, &c0);
    sincosf(a1, &s1, &c1);
    g_tab4[idx] = make_float4(c0, c1, s0, s1);
}

// ---------------- main split attention kernel ----------------
__global__ void __launch_bounds__(TPB, 3)
paged_attn_main(const float* __restrict__ query,
                const float* __restrict__ k_cache,
                const float* __restrict__ v_cache,
                const int*   __restrict__ slot_mapping,
                const int*   __restrict__ positions)
{
    const int cta   = blockIdx.x;
    const int split = cta & (SPLITS - 1);
    const int kvh   = (cta >> 3) & (KVHH - 1);
    const int b     = cta >> 6;
    const int tid   = threadIdx.x;
    const int w     = tid >> 5;
    const int lane  = tid & 31;

    __shared__ __align__(16) float4 s_scores[NWARPS][TPW];          // 4 KB
    __shared__ __align__(16) float  s_acc[REP][NWARPS][DD];         // 16 KB
    __shared__ float s_m[NWARPS][REP], s_l[NWARPS][REP];
    __shared__ float s_mstar[REP], s_f[NWARPS][REP];

    // ---- roped + pre-scaled Q; lane owns dims {2l, 2l+1, 2l+64, 2l+65} ----
    const int posQ = positions[b * SS + (SS - 1)];
    const float4 tq = g_tab4[posQ * 32 + lane];
    float4 qr[REP];
#pragma unroll
    for (int r = 0; r < REP; r++) {
        int h = kvh * REP + r;
        const float* qp = query + ((size_t)b * HH + h) * DD;
        float2 qlo = *(const float2*)(qp + 2 * lane);
        float2 qhi = *(const float2*)(qp + 64 + 2 * lane);
        float4 v;
        v.x = fmaf(-qhi.x, tq.z, qlo.x * tq.x) * SCALE_F;   // dim 2l
        v.y = fmaf(-qhi.y, tq.w, qlo.y * tq.y) * SCALE_F;   // dim 2l+1
        v.z = fmaf( qlo.x, tq.z, qhi.x * tq.x) * SCALE_F;   // dim 2l+64
        v.w = fmaf( qlo.y, tq.w, qhi.y * tq.y) * SCALE_F;   // dim 2l+65
        qr[r] = v;
    }

    const int sbase = split * CHUNK + w * TPW;
    const int* smap = slot_mapping + b * SS + sbase;
    const int* pmap = positions + b * SS + sbase;
    const float* kbase = k_cache + kvh * DD + 2 * lane;
    const float* vbase = v_cache + kvh * DD + 4 * lane;

    // ================= pass 1: K, scores -> smem, per-head max =================
    float mloc = -1e30f;
#pragma unroll 1
    for (int t0 = 0; t0 < TPW; t0 += 4) {
        int sl[4], ps[4];
#pragma unroll
        for (int u = 0; u < 4; u++) { sl[u] = __ldg(smap + t0 + u); ps[u] = __ldg(pmap + t0 + u); }
        float2 klo[4], khi[4];
        float4 tb[4];
#pragma unroll
        for (int u = 0; u < 4; u++) {
            klo[u] = make_float2(0.f, 0.f);
            khi[u] = make_float2(0.f, 0.f);
            if (sl[u] >= 0) {
                const float* kp = kbase + (size_t)sl[u] * (KVHH * DD);
                klo[u] = *(const float2*)kp;
                khi[u] = *(const float2*)(kp + 64);
            }
            tb[u] = g_tab4[ps[u] * 32 + lane];
        }
#pragma unroll
        for (int u = 0; u < 4; u++) {
            float kr0 = fmaf(-khi[u].x, tb[u].z, klo[u].x * tb[u].x);
            float kr1 = fmaf(-khi[u].y, tb[u].w, klo[u].y * tb[u].y);
            float kr2 = fmaf( klo[u].x, tb[u].z, khi[u].x * tb[u].x);
            float kr3 = fmaf( klo[u].y, tb[u].w, khi[u].y * tb[u].y);
            float v0 = fmaf(kr3, qr[0].w, fmaf(kr2, qr[0].z, fmaf(kr1, qr[0].y, kr0 * qr[0].x)));
            float v1 = fmaf(kr3, qr[1].w, fmaf(kr2, qr[1].z, fmaf(kr1, qr[1].y, kr0 * qr[1].x)));
            float v2 = fmaf(kr3, qr[2].w, fmaf(kr2, qr[2].z, fmaf(kr1, qr[2].y, kr0 * qr[2].x)));
            float v3 = fmaf(kr3, qr[3].w, fmaf(kr2, qr[3].z, fmaf(kr1, qr[3].y, kr0 * qr[3].x)));
            // width-folding reduce: 9 shuffles, lane(8h) ends owning head h's score
            float r0 = __shfl_xor_sync(0xffffffffu, v0, 16);
            float r1 = __shfl_xor_sync(0xffffffffu, v1, 16);
            float r2 = __shfl_xor_sync(0xffffffffu, v2, 16);
            float r3 = __shfl_xor_sync(0xffffffffu, v3, 16);
            float t0a = v0 + r0, t1a = v1 + r1, t2a = v2 + r2, t3a = v3 + r3;
            float a0 = (lane & 16) ? t2a : t0a;
            float a1 = (lane & 16) ? t3a : t1a;
            float u0 = a0 + __shfl_xor_sync(0xffffffffu, a0, 8);
            float u1 = a1 + __shfl_xor_sync(0xffffffffu, a1, 8);
            float bsum = (lane & 8) ? u1 : u0;
            bsum += __shfl_xor_sync(0xffffffffu, bsum, 4);
            bsum += __shfl_xor_sync(0xffffffffu, bsum, 2);
            bsum += __shfl_xor_sync(0xffffffffu, bsum, 1);
            mloc = fmaxf(mloc, bsum);
            if ((lane & 7) == 0) ((float*)&s_scores[w][t0 + u])[lane >> 3] = bsum;
        }
    }
    __syncwarp();
    const float m0 = __shfl_sync(0xffffffffu, mloc, 0);
    const float m1 = __shfl_sync(0xffffffffu, mloc, 8);
    const float m2 = __shfl_sync(0xffffffffu, mloc, 16);
    const float m3 = __shfl_sync(0xffffffffu, mloc, 24);

    // ================= pass 2: V, exp + accumulate =================
    float4 l4 = make_float4(0.f, 0.f, 0.f, 0.f);
    float4 acc0 = make_float4(0.f,0.f,0.f,0.f), acc1 = acc0, acc2 = acc0, acc3 = acc0;
#pragma unroll 1
    for (int t0 = 0; t0 < TPW; t0 += 4) {
        int sl[4];
#pragma unroll
        for (int u = 0; u < 4; u++) sl[u] = __ldg(smap + t0 + u);
        float4 vv[4], sc[4];
#pragma unroll
        for (int u = 0; u < 4; u++) {
            vv[u] = make_float4(0.f, 0.f, 0.f, 0.f);
            if (sl[u] >= 0) vv[u] = *(const float4*)(vbase + (size_t)sl[u] * (KVHH * DD));
            sc[u] = s_scores[w][t0 + u];
        }
#pragma unroll
        for (int u = 0; u < 4; u++) {
            float p0 = __expf(sc[u].x - m0);
            float p1 = __expf(sc[u].y - m1);
            float p2 = __expf(sc[u].z - m2);
            float p3 = __expf(sc[u].w - m3);
            l4.x += p0; l4.y += p1; l4.z += p2; l4.w += p3;
            float4 v4 = vv[u];
            acc0.x = fmaf(p0, v4.x, acc0.x); acc0.y = fmaf(p0, v4.y, acc0.y);
            acc0.z = fmaf(p0, v4.z, acc0.z); acc0.w = fmaf(p0, v4.w, acc0.w);
            acc1.x = fmaf(p1, v4.x, acc1.x); acc1.y = fmaf(p1, v4.y, acc1.y);
            acc1.z = fmaf(p1, v4.z, acc1.z); acc1.w = fmaf(p1, v4.w, acc1.w);
            acc2.x = fmaf(p2, v4.x, acc2.x); acc2.y = fmaf(p2, v4.y, acc2.y);
            acc2.z = fmaf(p2, v4.z, acc2.z); acc2.w = fmaf(p2, v4.w, acc2.w);
            acc3.x = fmaf(p3, v4.x, acc3.x); acc3.y = fmaf(p3, v4.y, acc3.y);
            acc3.z = fmaf(p3, v4.z, acc3.z); acc3.w = fmaf(p3, v4.w, acc3.w);
        }
    }

    // ---- per-warp state to smem ----
    if ((lane & 7) == 0) s_m[w][lane >> 3] = mloc;
    if (lane == 0) {
        s_l[w][0] = l4.x;   s_l[w][1] = l4.y;   s_l[w][2] = l4.z;   s_l[w][3] = l4.w;
    }
    *(float4*)&s_acc[0][w][lane * 4] = acc0;
    *(float4*)&s_acc[1][w][lane * 4] = acc1;
    *(float4*)&s_acc[2][w][lane * 4] = acc2;
    *(float4*)&s_acc[3][w][lane * 4] = acc3;
    __syncthreads();

    // ---- cross-warp softmax merge ----
    if (tid < REP) {
        float ms = -1e30f;
#pragma unroll
        for (int ww = 0; ww < NWARPS; ww++) ms = fmaxf(ms, s_m[ww][tid]);
        s_mstar[tid] = ms;
    }
    __syncthreads();
    if (tid < NWARPS * REP) {
        int ww = tid >> 2, h = tid & 3;
        s_f[ww][h] = __expf(s_m[ww][h] - s_mstar[h]);
    }
    __syncthreads();

    const size_t pidx = (size_t)((b * KVHH + kvh) * SPLITS + split);
    const size_t obase = pidx * (REP * DD);
    for (int idx = tid; idx < REP * DD; idx += TPB) {
        int h = idx >> 7, d = idx & (DD - 1);
        float v = 0.f;
#pragma unroll
        for (int ww = 0; ww < NWARPS; ww++) v = fmaf(s_f[ww][h], s_acc[h][ww][d], v);
        g_pacc[obase + idx] = v;
    }
    if (tid < REP) {
        float ls = 0.f;
#pragma unroll
        for (int ww = 0; ww < NWARPS; ww++) ls = fmaf(s_f[ww][tid], s_l[ww][tid], ls);
        g_pm[pidx * REP + tid] = s_mstar[tid];
        g_pl[pidx * REP + tid] = ls;
    }
}

// ---------------- split combine ----------------
__global__ void combine_kernel(float* __restrict__ out) {
    int idx = blockIdx.x * blockDim.x + threadIdx.x;
    if (idx >= BB * HH * DD) return;
    int d = idx & (DD - 1);
    int h = (idx >> 7) & (HH - 1);
    int b = idx >> 12;
    int kvh = h >> 2, r = h & 3;
    int pbase = (b * KVHH + kvh) * SPLITS;

    float mv[SPLITS];
    float ms = -1e30f;
#pragma unroll
    for (int s = 0; s < SPLITS; s++) {
        mv[s] = g_pm[(pbase + s) * REP + r];
        ms = fmaxf(ms, mv[s]);
    }
    float num = 0.f, den = 0.f;
#pragma unroll
    for (int s = 0; s < SPLITS; s++) {
        float f = __expf(mv[s] - ms);
        den = fmaf(f, g_pl[(pbase + s) * REP + r], den);
        num = fmaf(f, g_pacc[(size_t)(pbase + s) * REP * DD + r * DD + d], num);
    }
    out[idx] = num / den;
}

// ---------------- launch ----------------
extern "C" void kernel_launch(void* const* d_in, const int* in_sizes, int n_in,
                              void* d_out, int out_size) {
    const float* query  = (const float*)d_in[0];
    const float* kcache = (const float*)d_in[1];
    const float* vcache = (const float*)d_in[2];
    const int*   slots  = (const int*)d_in[3];
    const int*   poss   = (const int*)d_in[4];

    rope_table_kernel<<<(SS * 32 + 255) / 256, 256>>>();
    paged_attn_main<<<BB * KVHH * SPLITS, TPB>>>(query, kcache, vcache, slots, poss);
    combine_kernel<<<(BB * HH * DD + 255) / 256, 256>>>((float*)d_out);
}

// round 4
// speedup vs baseline: 1.4843x; 1.1399x over previous
#include <cuda_runtime.h>
#include <cstdint>

#define BB      32
#define HH      32
#define KVHH    8
#define DD      128
#define SS      2048
#define REP     4          // HH/KVHH
#define SPLITS  8
#define CHUNK   (SS/SPLITS)        // 256
#define TPB     256
#define NWARPS  8
#define TPW     (CHUNK/NWARPS)     // 32 tokens per warp
#define SCALE_F 0.08838834764831845f   // 1/sqrt(128)
#define ESHIFT  8.0f                   // uniform exp-arg shift; cancels in num/den

// ---------------- device scratch (no allocs allowed) ----------------
// tab4[pos][lane] = {cos(2l), cos(2l+1), sin(2l), sin(2l+1)}  (1 MB)
__device__ float4 g_tab4[SS * 32];
__device__ float g_pacc[BB * KVHH * SPLITS * REP * DD]; // 4 MB split partials (unnormalized)
__device__ float g_pl[BB * KVHH * SPLITS * REP];

// ---------------- rope table ----------------
__global__ void rope_table_kernel() {
    int idx = blockIdx.x * blockDim.x + threadIdx.x;    // SS*32
    if (idx >= SS * 32) return;
    int pos = idx >> 5, l = idx & 31;
    float inv0 = exp2f(-(float)(2 * l)     * (13.287712379549449f / 64.0f));
    float inv1 = exp2f(-(float)(2 * l + 1) * (13.287712379549449f / 64.0f));
    float a0 = (float)pos * inv0, a1 = (float)pos * inv1;
    float c0, s0, c1, s1;
    sincosf(a0, &s0, &c0);
    sincosf(a1, &s1, &c1);
    g_tab4[idx] = make_float4(c0, c1, s0, s1);
}

// ---------------- main split attention kernel (single pass, no max) ----------------
__global__ void __launch_bounds__(TPB, 3)
paged_attn_main(const float* __restrict__ query,
                const float* __restrict__ k_cache,
                const float* __restrict__ v_cache,
                const int*   __restrict__ slot_mapping,
                const int*   __restrict__ positions)
{
    const int cta   = blockIdx.x;
    const int split = cta & (SPLITS - 1);
    const int kvh   = (cta >> 3) & (KVHH - 1);
    const int b     = cta >> 6;
    const int tid   = threadIdx.x;
    const int w     = tid >> 5;
    const int lane  = tid & 31;

    __shared__ __align__(16) float s_acc[REP][NWARPS][DD];   // 16 KB
    __shared__ float s_l[NWARPS][REP];

    // ---- roped + pre-scaled Q; lane owns dims {2l, 2l+1, 2l+64, 2l+65} ----
    const int posQ = positions[b * SS + (SS - 1)];
    const float4 tq = g_tab4[posQ * 32 + lane];
    float4 qr[REP];
#pragma unroll
    for (int r = 0; r < REP; r++) {
        int h = kvh * REP + r;
        const float* qp = query + ((size_t)b * HH + h) * DD;
        float2 qlo = *(const float2*)(qp + 2 * lane);
        float2 qhi = *(const float2*)(qp + 64 + 2 * lane);
        float4 v;
        v.x = fmaf(-qhi.x, tq.z, qlo.x * tq.x) * SCALE_F;
        v.y = fmaf(-qhi.y, tq.w, qlo.y * tq.y) * SCALE_F;
        v.z = fmaf( qlo.x, tq.z, qhi.x * tq.x) * SCALE_F;
        v.w = fmaf( qlo.y, tq.w, qhi.y * tq.y) * SCALE_F;
        qr[r] = v;
    }

    const int sbase = split * CHUNK + w * TPW;
    const int* smap = slot_mapping + b * SS + sbase;
    const int* pmap = positions + b * SS + sbase;
    const float* kbase = k_cache + kvh * DD + 2 * lane;
    const float* vbase = v_cache + kvh * DD + 4 * lane;

    float lown = 0.f;   // per-lane-group l (group g == head g)
    float4 acc0 = make_float4(0.f,0.f,0.f,0.f), acc1 = acc0, acc2 = acc0, acc3 = acc0;

#pragma unroll 1
    for (int t0 = 0; t0 < TPW; t0 += 4) {
        int sl[4], ps[4];
#pragma unroll
        for (int u = 0; u < 4; u++) { sl[u] = __ldg(smap + t0 + u); ps[u] = __ldg(pmap + t0 + u); }
        float2 klo[4], khi[4];
        float4 vv[4], tb[4];
#pragma unroll
        for (int u = 0; u < 4; u++) {
            klo[u] = make_float2(0.f, 0.f);
            khi[u] = make_float2(0.f, 0.f);
            vv[u]  = make_float4(0.f, 0.f, 0.f, 0.f);
            if (sl[u] >= 0) {
                const float* kp = kbase + (size_t)sl[u] * (KVHH * DD);
                klo[u] = *(const float2*)kp;
                khi[u] = *(const float2*)(kp + 64);
                vv[u]  = *(const float4*)(vbase + (size_t)sl[u] * (KVHH * DD));
            }
            tb[u] = g_tab4[ps[u] * 32 + lane];
        }
#pragma unroll
        for (int u = 0; u < 4; u++) {
            // rope K in-lane
            float kr0 = fmaf(-khi[u].x, tb[u].z, klo[u].x * tb[u].x);
            float kr1 = fmaf(-khi[u].y, tb[u].w, klo[u].y * tb[u].y);
            float kr2 = fmaf( klo[u].x, tb[u].z, khi[u].x * tb[u].x);
            float kr3 = fmaf( klo[u].y, tb[u].w, khi[u].y * tb[u].y);
            // per-head partial dots
            float v0 = fmaf(kr3, qr[0].w, fmaf(kr2, qr[0].z, fmaf(kr1, qr[0].y, kr0 * qr[0].x)));
            float v1 = fmaf(kr3, qr[1].w, fmaf(kr2, qr[1].z, fmaf(kr1, qr[1].y, kr0 * qr[1].x)));
            float v2 = fmaf(kr3, qr[2].w, fmaf(kr2, qr[2].z, fmaf(kr1, qr[2].y, kr0 * qr[2].x)));
            float v3 = fmaf(kr3, qr[3].w, fmaf(kr2, qr[3].z, fmaf(kr1, qr[3].y, kr0 * qr[3].x)));
            // width-folding reduce: 9 shuffles; 8-lane group g ends with head g's full score
            float r0 = __shfl_xor_sync(0xffffffffu, v0, 16);
            float r1 = __shfl_xor_sync(0xffffffffu, v1, 16);
            float r2 = __shfl_xor_sync(0xffffffffu, v2, 16);
            float r3 = __shfl_xor_sync(0xffffffffu, v3, 16);
            float t0a = v0 + r0, t1a = v1 + r1, t2a = v2 + r2, t3a = v3 + r3;
            float a0 = (lane & 16) ? t2a : t0a;
            float a1 = (lane & 16) ? t3a : t1a;
            float u0 = a0 + __shfl_xor_sync(0xffffffffu, a0, 8);
            float u1 = a1 + __shfl_xor_sync(0xffffffffu, a1, 8);
            float bsum = (lane & 8) ? u1 : u0;
            bsum += __shfl_xor_sync(0xffffffffu, bsum, 4);
            bsum += __shfl_xor_sync(0xffffffffu, bsum, 2);
            bsum += __shfl_xor_sync(0xffffffffu, bsum, 1);
            // one exp per token (per owning group), then broadcast the 4 head p's
            float p = __expf(bsum - ESHIFT);
            lown += p;
            int src = lane & 7;
            float p0 = __shfl_sync(0xffffffffu, p, src);
            float p1 = __shfl_sync(0xffffffffu, p, src | 8);
            float p2 = __shfl_sync(0xffffffffu, p, src | 16);
            float p3 = __shfl_sync(0xffffffffu, p, src | 24);
            float4 v4 = vv[u];
            acc0.x = fmaf(p0, v4.x, acc0.x); acc0.y = fmaf(p0, v4.y, acc0.y);
            acc0.z = fmaf(p0, v4.z, acc0.z); acc0.w = fmaf(p0, v4.w, acc0.w);
            acc1.x = fmaf(p1, v4.x, acc1.x); acc1.y = fmaf(p1, v4.y, acc1.y);
            acc1.z = fmaf(p1, v4.z, acc1.z); acc1.w = fmaf(p1, v4.w, acc1.w);
            acc2.x = fmaf(p2, v4.x, acc2.x); acc2.y = fmaf(p2, v4.y, acc2.y);
            acc2.z = fmaf(p2, v4.z, acc2.z); acc2.w = fmaf(p2, v4.w, acc2.w);
            acc3.x = fmaf(p3, v4.x, acc3.x); acc3.y = fmaf(p3, v4.y, acc3.y);
            acc3.z = fmaf(p3, v4.z, acc3.z); acc3.w = fmaf(p3, v4.w, acc3.w);
        }
    }

    // ---- per-warp state to smem ----
    if ((lane & 7) == 0) s_l[w][lane >> 3] = lown;
    *(float4*)&s_acc[0][w][lane * 4] = acc0;
    *(float4*)&s_acc[1][w][lane * 4] = acc1;
    *(float4*)&s_acc[2][w][lane * 4] = acc2;
    *(float4*)&s_acc[3][w][lane * 4] = acc3;
    __syncthreads();

    // ---- cross-warp merge (plain sums; no factors needed) ----
    const size_t pidx = (size_t)((b * KVHH + kvh) * SPLITS + split);
    const size_t obase = pidx * (REP * DD);
    for (int idx = tid; idx < REP * DD; idx += TPB) {
        int h = idx >> 7, d = idx & (DD - 1);
        float v = 0.f;
#pragma unroll
        for (int ww = 0; ww < NWARPS; ww++) v += s_acc[h][ww][d];
        g_pacc[obase + idx] = v;
    }
    if (tid < REP) {
        float ls = 0.f;
#pragma unroll
        for (int ww = 0; ww < NWARPS; ww++) ls += s_l[ww][tid];
        g_pl[pidx * REP + tid] = ls;
    }
}

// ---------------- split combine ----------------
__global__ void combine_kernel(float* __restrict__ out) {
    int idx = blockIdx.x * blockDim.x + threadIdx.x;
    if (idx >= BB * HH * DD) return;
    int d = idx & (DD - 1);
    int h = (idx >> 7) & (HH - 1);
    int b = idx >> 12;
    int kvh = h >> 2, r = h & 3;
    int pbase = (b * KVHH + kvh) * SPLITS;

    float num = 0.f, den = 0.f;
#pragma unroll
    for (int s = 0; s < SPLITS; s++) {
        den += g_pl[(pbase + s) * REP + r];
        num += g_pacc[(size_t)(pbase + s) * REP * DD + r * DD + d];
    }
    out[idx] = num / den;
}

// ---------------- launch ----------------
extern "C" void kernel_launch(void* const* d_in, const int* in_sizes, int n_in,
                              void* d_out, int out_size) {
    const float* query  = (const float*)d_in[0];
    const float* kcache = (const float*)d_in[1];
    const float* vcache = (const float*)d_in[2];
    const int*   slots  = (const int*)d_in[3];
    const int*   poss   = (const int*)d_in[4];

    rope_table_kernel<<<(SS * 32 + 255) / 256, 256>>>();
    paged_attn_main<<<BB * KVHH * SPLITS, TPB>>>(query, kcache, vcache, slots, poss);
    combine_kernel<<<(BB * HH * DD + 255) / 256, 256>>>((float*)d_out);
}